// round 17
// baseline (speedup 1.0000x reference)
#include <cuda_runtime.h>
#include <math.h>

#define Bn 128
#define Cn 48
#define Hn 64
#define Wn 64
#define Pn 32
#define OUT_ELEMS (Bn*Cn*Hn*Wn)

// Scratch (no allocations allowed). All zero-init; tail resets for replays.
__device__ unsigned long long g_M2[Cn*Cn];   // M duplicated (m,m) as f32x2
__device__ float g_S[256][4];                // combined score sums per (b*2+g)
__device__ int g_pcnt[256];                  // per-pair partial arrivals
__device__ int g_flag;                       // M-ready arrivals
__device__ int g_done;                       // CTA completion arrivals

#define FMA2(acc, mm, vv) asm("fma.rn.f32x2 %0, %1, %2, %0;" : "+l"(acc) : "l"(mm), "l"(vv))
#define PACK2(dst, lo, hi) asm("mov.b64 %0, {%1,%2};" : "=l"(dst) : "f"(lo), "f"(hi))
#define UNPACK2(lo, hi, src) asm("mov.b64 {%0,%1}, %2;" : "=f"(lo), "=f"(hi) : "l"(src))

// ---------------------------------------------------------------------------
// SINGLE FUSED KERNEL. 512 CTAs x 256 threads, CTA = (b, g, khalf h).
// Each CTA: [bid<9: compute M slice] -> stage V(first kq) -> wait M ->
// score 2 kq chunks -> atomicAdd partial into g_S[pair] -> wait pair ->
// softmax coeffs -> phase-2 output for its half -> tail CTA does logdet+reset.
// ---------------------------------------------------------------------------
__global__ __launch_bounds__(256, 3) void fused_kernel(
        const float* __restrict__ x,
        const float* __restrict__ logdet_in,
        const float* __restrict__ Wq1, const float* __restrict__ Wq2,
        const float* __restrict__ Wq3, const float* __restrict__ Wk1,
        const float* __restrict__ Wk2, const float* __restrict__ Wk3,
        const float* __restrict__ off1p, const float* __restrict__ off2p,
        const float* __restrict__ off3p,
        float* __restrict__ out, int out_size) {
    __shared__ unsigned long long sV[Cn*128];   // 49152 B (union: W mats 0..4)
    __shared__ unsigned long long sM2[Cn*Cn];   // 18432 B (union: W mat 5)
    __shared__ float4 sred[8];
    __shared__ float sc[4];
    __shared__ int s_last;

    const int bid = blockIdx.x;
    const int h    = bid & 1;          // k-half: kq in {2h, 2h+1}
    const int pair = bid >> 1;         // (b*2+g)
    const int g = pair & 1;
    const int b = pair >> 1;
    const int tid = threadIdx.x;
    const int ci = tid >> 5;
    const int kl = tid & 31;

    // ---- M producers: CTAs 0..8 (stage W in smem, compute from smem) ----
    if (bid < 9) {
        float* swA = (float*)sV;     // matrices 0..4
        float* swB = (float*)sM2;    // matrix 5
        #pragma unroll
        for (int half = 0; half < 2; ++half) {
            float4 regs[7];
            #pragma unroll
            for (int k = 0; k < 7; ++k) {
                int idx = tid + (half*7 + k)*256;
                if (idx < 3456) {
                    int m = idx / 576, off = idx % 576;
                    const float4* p;
                    switch (m) {
                        case 0:  p = (const float4*)Wq1; break;
                        case 1:  p = (const float4*)Wk1; break;
                        case 2:  p = (const float4*)Wq2; break;
                        case 3:  p = (const float4*)Wk2; break;
                        case 4:  p = (const float4*)Wq3; break;
                        default: p = (const float4*)Wk3; break;
                    }
                    regs[k] = p[off];
                }
            }
            #pragma unroll
            for (int k = 0; k < 7; ++k) {
                int idx = tid + (half*7 + k)*256;
                if (idx < 3456) {
                    int m = idx / 576, off = idx % 576;
                    float* dst = (m < 5) ? (swA + m*2304 + off*4) : (swB + off*4);
                    float4 v = regs[k];
                    dst[0]=v.x; dst[1]=v.y; dst[2]=v.z; dst[3]=v.w;
                }
            }
        }
        __syncthreads();
        int e = bid*256 + tid;                 // 0..2303
        int c = e / Cn, c2 = e % Cn;
        float s = 0.f;
        #pragma unroll
        for (int o = 0; o < Cn; ++o) {
            s += swA[0*2304 + o*Cn + c]*swA[1*2304 + o*Cn + c2]
               + swA[2*2304 + o*Cn + c]*swA[3*2304 + o*Cn + c2]
               + swA[4*2304 + o*Cn + c]*swB[o*Cn + c2];
        }
        s *= (1.0f / sqrtf((float)(Cn*Pn*Pn)));
        ((float2*)g_M2)[e] = make_float2(s, s);
        __threadfence();
        __syncthreads();                       // sV/sM2 reusable after this
        if (tid == 0) atomicAdd(&g_flag, 1);
    }

    const float2* xb2 = (const float2*)(x + (size_t)b * Cn * Hn * Wn);
    const int kq0 = 2*h;

    // ---- V staging for first kq (independent of M) ----
    #pragma unroll
    for (int bt = 0; bt < 3; ++bt) {
        float2 ra[8], rb[8];
        #pragma unroll
        for (int k = 0; k < 8; ++k) {
            int idx = tid + (bt*8 + k)*256;
            int c2 = idx >> 7;
            int kk = idx & 127;
            int yy = kk >> 4;
            int xx = kk & 15;
            int yt = kq0*8 + yy;
            ra[k] = xb2[((size_t)c2*Hn + yt)*32      + g*16 + xx];
            rb[k] = xb2[((size_t)c2*Hn + yt + 32)*32 + g*16 + xx];
        }
        #pragma unroll
        for (int k = 0; k < 8; ++k) {
            int idx = tid + (bt*8 + k)*256;
            unsigned long long pk;
            if (g == 0) PACK2(pk, ra[k].x, rb[k].x);
            else        PACK2(pk, ra[k].y, rb[k].y);
            sV[idx] = pk;
        }
    }

    // ---- wait for M, then load it to smem ----
    if (tid == 0) {
        while (atomicAdd(&g_flag, 0) < 9) { }
    }
    __syncthreads();
    __threadfence();
    {
        unsigned long long m[9];
        #pragma unroll
        for (int k = 0; k < 9; ++k) m[k] = g_M2[tid + k*256];
        #pragma unroll
        for (int k = 0; k < 9; ++k) sM2[tid + k*256] = m[k];
    }

    float p00 = 0.f, p01 = 0.f, p10 = 0.f, p11 = 0.f;

    #pragma unroll
    for (int kqi = 0; kqi < 2; ++kqi) {
        __syncthreads();   // staged sV (and sM2 on first iter) visible

        unsigned long long acc[24];
        #pragma unroll
        for (int i = 0; i < 24; ++i) acc[i] = 0ULL;

        #pragma unroll
        for (int c2 = 0; c2 < Cn; ++c2) {
            unsigned long long v0 = sV[c2*128 + kl];
            unsigned long long v1 = sV[c2*128 + kl + 32];
            unsigned long long v2 = sV[c2*128 + kl + 64];
            unsigned long long v3 = sV[c2*128 + kl + 96];
            #pragma unroll
            for (int r = 0; r < 6; ++r) {
                unsigned long long m = sM2[(ci*6 + r)*Cn + c2];   // broadcast
                FMA2(acc[r*4    ], m, v0);
                FMA2(acc[r*4 + 1], m, v1);
                FMA2(acc[r*4 + 2], m, v2);
                FMA2(acc[r*4 + 3], m, v3);
            }
        }

        #pragma unroll
        for (int r = 0; r < 6; ++r) {
            #pragma unroll
            for (int j = 0; j < 4; ++j) {
                float wt, wb, vt, vb;
                UNPACK2(wt, wb, acc[r*4 + j]);
                unsigned long long v = sV[(ci*6 + r)*128 + kl + j*32];
                UNPACK2(vt, vb, v);
                p00 = fmaf(vt, wt, p00);  p01 = fmaf(vt, wb, p01);
                p10 = fmaf(vb, wt, p10);  p11 = fmaf(vb, wb, p11);
            }
        }

        if (kqi == 0) {
            __syncthreads();   // all readers of sV done before restage
            int kqn = kq0 + 1;
            #pragma unroll
            for (int bt = 0; bt < 3; ++bt) {
                float2 ra[8], rb[8];
                #pragma unroll
                for (int k = 0; k < 8; ++k) {
                    int idx = tid + (bt*8 + k)*256;
                    int c2 = idx >> 7;
                    int kk = idx & 127;
                    int yy = kk >> 4;
                    int xx = kk & 15;
                    int yt = kqn*8 + yy;
                    ra[k] = xb2[((size_t)c2*Hn + yt)*32      + g*16 + xx];
                    rb[k] = xb2[((size_t)c2*Hn + yt + 32)*32 + g*16 + xx];
                }
                #pragma unroll
                for (int k = 0; k < 8; ++k) {
                    int idx = tid + (bt*8 + k)*256;
                    unsigned long long pk;
                    if (g == 0) PACK2(pk, ra[k].x, rb[k].x);
                    else        PACK2(pk, ra[k].y, rb[k].y);
                    sV[idx] = pk;
                }
            }
        }
    }

    // reduce partials across the block (deterministic)
    #pragma unroll
    for (int off = 16; off; off >>= 1) {
        p00 += __shfl_xor_sync(0xffffffffu, p00, off);
        p01 += __shfl_xor_sync(0xffffffffu, p01, off);
        p10 += __shfl_xor_sync(0xffffffffu, p10, off);
        p11 += __shfl_xor_sync(0xffffffffu, p11, off);
    }
    if (kl == 0) sred[ci] = make_float4(p00, p01, p10, p11);
    __syncthreads();

    // combine with partner CTA via atomics (2 addends -> deterministic)
    if (tid == 0) {
        float4 sv = sred[0];
        #pragma unroll
        for (int w = 1; w < 8; ++w) {
            float4 t = sred[w];
            sv.x += t.x; sv.y += t.y; sv.z += t.z; sv.w += t.w;
        }
        atomicAdd(&g_S[pair][0], sv.x);
        atomicAdd(&g_S[pair][1], sv.y);
        atomicAdd(&g_S[pair][2], sv.z);
        atomicAdd(&g_S[pair][3], sv.w);
        __threadfence();
        atomicAdd(&g_pcnt[pair], 1);
        while (atomicAdd(&g_pcnt[pair], 0) < 2) { }
        __threadfence();

        const float off  = off1p[0];
        const float off2 = off2p[0];
        const float off3 = off3p[0];
        float stt = g_S[pair][0] + off3, stb = g_S[pair][1] + off3;
        float sbt = g_S[pair][2] + off3, sbb = g_S[pair][3] + off3;
        float z = off3;

        float mx  = fmaxf(fmaxf(stt, stb), z);
        float e0  = expf(stt-mx), e1 = expf(stb-mx), ez = expf(z-mx);
        float inv = 1.f / (e0 + e1 + 2.f*ez);
        sc[0] = e0*inv + off2 + off;         // a_tt
        sc[1] = e1*inv + off2;               // a_tb

        mx  = fmaxf(fmaxf(sbt, sbb), z);
        e0  = expf(sbt-mx); e1 = expf(sbb-mx); ez = expf(z-mx);
        inv = 1.f / (e0 + e1 + 2.f*ez);
        sc[2] = e0*inv + off2;               // a_bt
        sc[3] = e1*inv + off2 + off;         // a_bb
    }
    __syncthreads();

    // ---- Phase 2: output for (b, column-block g), this CTA's half ----
    const float a_tt = sc[0], a_tb = sc[1], a_bt = sc[2], a_bb = sc[3];
    const float4* xp = (const float4*)(x + (size_t)b * Cn * Hn * Wn);
    float4* op = (float4*)(out + (size_t)b * Cn * Hn * Wn);

    #pragma unroll 4
    for (int i = h*24; i < h*24 + 24; ++i) {
        int idx = tid + i*256;               // 12288 float4-pairs total per (b,g)
        int x4l = idx & 7;
        int y   = (idx >> 3) & 31;
        int c   = idx >> 8;
        int fo  = (c*Hn + y)*16 + g*8 + x4l; // float4 offset
        float4 xt = xp[fo];
        float4 xb = xp[fo + 32*16];
        float4 ot, ob;
        if (g == 0) {  // pass-through at even columns (x,z)
            ot.x = xt.x;                    ob.x = xb.x;
            ot.y = a_tt*xt.y + a_tb*xb.y;   ob.y = a_bt*xt.y + a_bb*xb.y;
            ot.z = xt.z;                    ob.z = xb.z;
            ot.w = a_tt*xt.w + a_tb*xb.w;   ob.w = a_bt*xt.w + a_bb*xb.w;
        } else {       // pass-through at odd columns (y,w)
            ot.x = a_tt*xt.x + a_tb*xb.x;   ob.x = a_bt*xt.x + a_bb*xb.x;
            ot.y = xt.y;                    ob.y = xb.y;
            ot.z = a_tt*xt.z + a_tb*xb.z;   ob.z = a_bt*xt.z + a_bb*xb.z;
            ot.w = xt.w;                    ob.w = xb.w;
        }
        __stwt(&op[fo], ot);
        __stwt(&op[fo + 32*16], ob);
    }

    // ---- Tail: last CTA computes logdet + resets all state for replay ----
    __threadfence();
    __syncthreads();
    if (tid == 0) {
        int old = atomicAdd(&g_done, 1);
        s_last = (old == 511);
    }
    __syncthreads();
    if (s_last) {
        __threadfence();
        if (tid < Bn) {
            int bb = tid;
            const float off  = off1p[0];
            const float off2 = off2p[0];
            const float off3 = off3p[0];
            float ld = logdet_in[bb];
            #pragma unroll
            for (int gg = 0; gg < 2; ++gg) {
                float stt = g_S[bb*2+gg][0] + off3, stb = g_S[bb*2+gg][1] + off3;
                float sbt = g_S[bb*2+gg][2] + off3, sbb = g_S[bb*2+gg][3] + off3;
                float z = off3;

                float mx  = fmaxf(fmaxf(stt, stb), z);
                float e0  = expf(stt-mx), e1 = expf(stb-mx), ez = expf(z-mx);
                float inv = 1.f / (e0 + e1 + 2.f*ez);
                float a_tt2 = e0*inv + off2 + off;
                float a_tb2 = e1*inv + off2;

                mx  = fmaxf(fmaxf(sbt, sbb), z);
                e0  = expf(sbt-mx); e1 = expf(sbb-mx); ez = expf(z-mx);
                inv = 1.f / (e0 + e1 + 2.f*ez);
                float a_bt2 = e0*inv + off2;
                float a_bb2 = e1*inv + off2 + off;

                float det = a_tt2*a_bb2 - a_tb2*a_bt2;
                ld += logf(fabsf(det)) * (float)(Pn*(Pn/2)*Cn);
            }
            if (OUT_ELEMS + bb < out_size) out[OUT_ELEMS + bb] = ld;
        }
        __syncthreads();
        // reset all cross-CTA state for the next graph replay
        if (tid < 256) {
            g_S[tid][0] = 0.f; g_S[tid][1] = 0.f;
            g_S[tid][2] = 0.f; g_S[tid][3] = 0.f;
            g_pcnt[tid] = 0;
        }
        __syncthreads();
        if (tid == 0) { g_flag = 0; g_done = 0; }
    }
}

// ---------------------------------------------------------------------------
extern "C" void kernel_launch(void* const* d_in, const int* in_sizes, int n_in,
                              void* d_out, int out_size) {
    const float* x      = (const float*)d_in[0];
    const float* logdet = (const float*)d_in[1];
    const float* Wq1    = (const float*)d_in[2];
    const float* Wq2    = (const float*)d_in[3];
    const float* Wq3    = (const float*)d_in[4];
    const float* Wk1    = (const float*)d_in[5];
    const float* Wk2    = (const float*)d_in[6];
    const float* Wk3    = (const float*)d_in[7];
    const float* off1   = (const float*)d_in[8];
    const float* off2   = (const float*)d_in[9];
    const float* off3   = (const float*)d_in[10];
    float* out = (float*)d_out;

    fused_kernel<<<512, 256>>>(x, logdet, Wq1, Wq2, Wq3, Wk1, Wk2, Wk3,
                               off1, off2, off3, out, out_size);
}